// round 13
// baseline (speedup 1.0000x reference)
#include <cuda_runtime.h>
#include <cuda_bf16.h>
#include <mma.h>
#include <cstdint>

using namespace nvcuda;

#define NROWS 2048
#define DIM   1024

// Packed slab layout: matrix [Rpad, K] (K-major) stored as slabs of 128 rows x 64 K.
// Within a row-tile rt, slab kt lives at ((rt*ld)+kt)*SLAB_ELEMS (ld = slabs per row-tile).
// Row r at r*72 elems (144B stride), col c at +c. Slab = 18432B contiguous -> one bulk copy.
#define SLAB_ELEMS 9216
#define SLAB_BYTES 18432
#define NSTAGE 3

// ================= helpers =================
__device__ __forceinline__ uint32_t smem_u32(const void* p) {
    uint32_t a;
    asm("{ .reg .u64 t; cvta.to.shared.u64 t, %1; cvt.u32.u64 %0, t; }" : "=r"(a) : "l"(p));
    return a;
}
#define MBARRIER_INIT(mbar, cnt) \
    asm volatile("mbarrier.init.shared.b64 [%0], %1;" \
                 :: "r"((uint32_t)(mbar)), "r"((uint32_t)(cnt)) : "memory")
#define MBARRIER_EXPECT_TX(mbar, tx) \
    asm volatile("mbarrier.arrive.expect_tx.shared.b64 _, [%0], %1;" \
                 :: "r"((uint32_t)(mbar)), "r"((uint32_t)(tx)) : "memory")
#define MBARRIER_WAIT_PARITY(mbar, par) do { \
    uint32_t _m = (uint32_t)(mbar); uint32_t _p = (uint32_t)(par); uint32_t _d; \
    asm volatile("{\n\t.reg .pred p;\n\t" \
        "mbarrier.try_wait.parity.acquire.cta.shared::cta.b64 p, [%1], %2;\n\t" \
        "selp.b32 %0, 1, 0, p;\n\t}" : "=r"(_d) : "r"(_m), "r"(_p) : "memory"); \
    if (!_d) { \
        asm volatile("{\n\t.reg .pred P1;\n\t" \
            "WL_%=:\n\t" \
            "mbarrier.try_wait.parity.acquire.cta.shared::cta.b64 P1, [%0], %1, 0x989680;\n\t" \
            "@P1 bra.uni WD_%=;\n\t" \
            "bra.uni WL_%=;\n\t" \
            "WD_%=:\n\t}" :: "r"(_m), "r"(_p) : "memory"); \
    } \
} while (0)
__device__ __forceinline__ void bulk_g2s(uint32_t dst, const void* src, uint32_t bytes,
                                         uint32_t mbar) {
    asm volatile(
        "cp.async.bulk.shared::cluster.global.mbarrier::complete_tx::bytes [%0], [%1], %2, [%3];"
        :: "r"(dst), "l"(src), "r"(bytes), "r"(mbar) : "memory");
}

// ================= packed scratch buffers (bf16) =================
__device__ __align__(256) __nv_bfloat16 g_hP   [16 * 16 * SLAB_ELEMS];   // h [2048,1024]
__device__ __align__(256) __nv_bfloat16 g_pT   [11 * 16 * SLAB_ELEMS];   // projT cat [1408,1024]
__device__ __align__(256) __nv_bfloat16 g_w0P  [157 * 16 * SLAB_ELEMS];
__device__ __align__(256) __nv_bfloat16 g_w1P  [235 *  4 * SLAB_ELEMS];
__device__ __align__(256) __nv_bfloat16 g_w2P  [391 *  1 * SLAB_ELEMS];
__device__ __align__(256) __nv_bfloat16 g_hpAll[16 * 22 * SLAB_ELEMS];   // hp cat [2048,1408]
__device__ __align__(256) float g_sum0[NROWS];
__device__ __align__(256) float g_sum1[NROWS];
__device__ __align__(256) float g_sum2[NROWS];
__device__ __align__(256) float g_selh [NROWS];
__device__ __align__(256) float g_selv1[NROWS];
__device__ __align__(256) float g_selv2[NROWS];
__device__ __align__(256) int   g_selc0[NROWS];
__device__ __align__(256) int   g_selc1[NROWS];
__device__ __align__(256) int   g_selc2[NROWS];
__device__ __align__(256) int   g_tgt  [NROWS];

// ======== packAll: 4 row-major fp32 matrices -> packed bf16 slabs in ONE launch ==========
__global__ void k_packAll(const float* __restrict__ h,  __nv_bfloat16* __restrict__ hP,
                          const float* __restrict__ w0, __nv_bfloat16* __restrict__ w0P,
                          const float* __restrict__ w1, __nv_bfloat16* __restrict__ w1P,
                          const float* __restrict__ w2, __nv_bfloat16* __restrict__ w2P)
{
    const float* src; __nv_bfloat16* dst; int R, K, tiles;
    switch (blockIdx.z) {
        case 0: src = h;  dst = hP;  R = 2048;  K = 1024; tiles = 16;  break;
        case 1: src = w0; dst = w0P; R = 20000; K = 1024; tiles = 157; break;
        case 2: src = w1; dst = w1P; R = 30000; K = 256;  tiles = 235; break;
        default:src = w2; dst = w2P; R = 50000; K = 64;   tiles = 391; break;
    }
    if ((int)blockIdx.y >= tiles) return;
    int chunksPerRow = K >> 3;
    int shift = 31 - __clz(chunksPerRow);
    int blockChunks = chunksPerRow << 7;
    int rbase = blockIdx.y << 7;
    for (int idx = blockIdx.x * blockDim.x + threadIdx.x; idx < blockChunks;
         idx += gridDim.x * blockDim.x) {
        int rloc = idx >> shift;
        int c    = idx & (chunksPerRow - 1);
        int r    = rbase + rloc;
        int kt = c >> 3, ci = c & 7;
        size_t doff = ((size_t)blockIdx.y * (K >> 6) + kt) * SLAB_ELEMS
                      + (size_t)rloc * 72 + ci * 8;
        uint4 o = make_uint4(0u, 0u, 0u, 0u);
        if (r < R) {
            const float4* s = reinterpret_cast<const float4*>(src + (size_t)r * K + c * 8);
            float4 v0 = s[0], v1 = s[1];
            __nv_bfloat162 b0 = __floats2bfloat162_rn(v0.x, v0.y);
            __nv_bfloat162 b1 = __floats2bfloat162_rn(v0.z, v0.w);
            __nv_bfloat162 b2 = __floats2bfloat162_rn(v1.x, v1.y);
            __nv_bfloat162 b3 = __floats2bfloat162_rn(v1.z, v1.w);
            o.x = *reinterpret_cast<uint32_t*>(&b0);
            o.y = *reinterpret_cast<uint32_t*>(&b1);
            o.z = *reinterpret_cast<uint32_t*>(&b2);
            o.w = *reinterpret_cast<uint32_t*>(&b3);
        }
        *reinterpret_cast<uint4*>(dst + doff) = o;
    }
}

// ======== packT_init: transpose-pack p0|p1|p2 -> g_pT [1408,1024] + target decode =========
__global__ void k_packT_init(const float* __restrict__ p0, const float* __restrict__ p1,
                             const float* __restrict__ p2, __nv_bfloat16* __restrict__ pT,
                             const int* __restrict__ t32)
{
    if (blockIdx.x == 44) {
        if (blockIdx.y != 0) return;
        int tid = threadIdx.y * 32 + threadIdx.x;
        __shared__ int s_nonzero_odd;
        if (tid == 0) s_nonzero_odd = 0;
        __syncthreads();
        for (int i = tid; i < NROWS / 2; i += 256)
            if (t32[2 * i + 1] != 0) atomicOr(&s_nonzero_odd, 1);
        __syncthreads();
        bool is64 = (s_nonzero_odd == 0);
        for (int r = tid; r < NROWS; r += 256) {
            int t = is64 ? t32[2 * r] : t32[r];
            g_tgt[r] = t;
            g_sum0[r] = 0.f; g_sum1[r] = 0.f; g_sum2[r] = 0.f;
            g_selc0[r] = (t < 20000) ? t : -1;
            int t1 = t - 20000; if (t1 < 0) t1 = 0; if (t1 > 29999) t1 = 29999;
            g_selc1[r] = t1;
            int t2 = t - 50000; if (t2 < 0) t2 = 0; if (t2 > 49999) t2 = 49999;
            g_selc2[r] = t2;
        }
        return;
    }
    __shared__ float t[32][33];
    int n0 = blockIdx.x * 32, k0 = blockIdx.y * 32;
    int x = threadIdx.x, y = threadIdx.y;
    #pragma unroll
    for (int i = 0; i < 32; i += 8) {
        int k = k0 + y + i, n = n0 + x;
        float v;
        if (n < 1024)       v = p0[(size_t)k * 1024 + n];
        else if (n < 1280)  v = p1[(size_t)k * 256 + (n - 1024)];
        else if (n < 1344)  v = p2[(size_t)k * 64 + (n - 1280)];
        else                v = 0.f;
        t[y + i][x] = v;
    }
    __syncthreads();
    #pragma unroll
    for (int i = 0; i < 32; i += 8) {
        int n = n0 + y + i, k = k0 + x;
        size_t doff = ((size_t)(n >> 7) * 16 + (k >> 6)) * SLAB_ELEMS
                      + (size_t)(n & 127) * 72 + (k & 63);
        pT[doff] = __float2bfloat16(t[x][y + i]);
    }
}

// ================= shared GEMM mainloop (3-stage bulk pipeline, 4 warps, 64x64/warp) ======
// 128x128 tile: acc = A_tile @ B_tile^T over KT 64-K slabs. 128 threads.
struct AccTile {
    wmma::fragment<wmma::accumulator, 16, 16, 16, float> a[4][4];
};
__device__ __forceinline__ void gemm_mainloop(
    AccTile& T, char* dsm, uint32_t sb,
    const __nv_bfloat16* A, const __nv_bfloat16* B,
    int rowTile, int colTile, int ldA, int ldB, int KT,
    int tid, int wm, int wn)
{
    auto slabA = [&](int s) {
        return reinterpret_cast<const __nv_bfloat16*>(dsm + 1024 + s * 2 * SLAB_BYTES);
    };
    auto slabB = [&](int s) {
        return reinterpret_cast<const __nv_bfloat16*>(dsm + 1024 + s * 2 * SLAB_BYTES + SLAB_BYTES);
    };
    auto issue = [&](int kt, int s) {
        uint32_t mb = sb + (uint32_t)s * 8;
        MBARRIER_EXPECT_TX(mb, 2 * SLAB_BYTES);
        const char* aS = reinterpret_cast<const char*>(A)
                         + ((size_t)rowTile * ldA + kt) * SLAB_BYTES;
        const char* bS = reinterpret_cast<const char*>(B)
                         + ((size_t)colTile * ldB + kt) * SLAB_BYTES;
        bulk_g2s(smem_u32(slabA(s)), aS, SLAB_BYTES, mb);
        bulk_g2s(smem_u32(slabB(s)), bS, SLAB_BYTES, mb);
    };
    if (tid == 0) {
        #pragma unroll
        for (int s = 0; s < NSTAGE; s++)
            if (s < KT) issue(s, s);
    }

    #pragma unroll
    for (int fm = 0; fm < 4; fm++)
        #pragma unroll
        for (int fn = 0; fn < 4; fn++)
            wmma::fill_fragment(T.a[fm][fn], 0.f);

    int s = 0, ph = 0;
    for (int kt = 0; kt < KT; kt++) {
        MBARRIER_WAIT_PARITY(sb + (uint32_t)s * 8, ph);
        const __nv_bfloat16* As = slabA(s);
        const __nv_bfloat16* Bs = slabB(s);
        #pragma unroll
        for (int kk = 0; kk < 64; kk += 16) {
            wmma::fragment<wmma::matrix_a, 16, 16, 16, __nv_bfloat16, wmma::row_major> af[4];
            #pragma unroll
            for (int fm = 0; fm < 4; fm++)
                wmma::load_matrix_sync(af[fm], As + (wm * 64 + fm * 16) * 72 + kk, 72);
            #pragma unroll
            for (int fn = 0; fn < 4; fn++) {
                wmma::fragment<wmma::matrix_b, 16, 16, 16, __nv_bfloat16, wmma::col_major> bf;
                wmma::load_matrix_sync(bf, Bs + (wn * 64 + fn * 16) * 72 + kk, 72);
                #pragma unroll
                for (int fm = 0; fm < 4; fm++)
                    wmma::mma_sync(T.a[fm][fn], af[fm], bf, T.a[fm][fn]);
            }
        }
        __syncthreads();   // slab s consumed by all warps
        if (tid == 0 && kt + NSTAGE < KT) issue(kt + NSTAGE, s);
        if (++s == NSTAGE) { s = 0; ph ^= 1; }
    }
}

// ================= merged logit GEMM: head + tail1 + tail2 in ONE launch =================
// grid (157+235+391, 16), 128 threads. Segment from blockIdx.x. Fused exp epilogue.
__global__ void __launch_bounds__(128, 2)
k_logit(const __nv_bfloat16* __restrict__ hpAll,
        const __nv_bfloat16* __restrict__ w0P, const float* __restrict__ b0,
        const __nv_bfloat16* __restrict__ w1P, const float* __restrict__ b1,
        const __nv_bfloat16* __restrict__ w2P, const float* __restrict__ b2)
{
    extern __shared__ __align__(128) char dsm[];
    const uint32_t sb = smem_u32(dsm);
    float* biasS = reinterpret_cast<float*>(dsm + 64);

    const int tid  = threadIdx.x;
    const int warp = tid >> 5;
    const int lane = tid & 31;
    const int wm   = warp >> 1;   // 0..1 -> rows wm*64
    const int wn   = warp & 1;    // 0..1 -> cols wn*64

    int x = blockIdx.x;
    int xo;
    const __nv_bfloat16* B; const float* bias;
    const int* selc; float* selv; float* sumexp;
    int N, KT, aoff;
    if (x < 157) {
        xo = x; B = w0P; bias = b0; N = 20000; KT = 16; aoff = 0;
        selc = g_selc0; selv = g_selh; sumexp = g_sum0;
    } else if (x < 392) {
        xo = x - 157; B = w1P; bias = b1; N = 30000; KT = 4; aoff = 16;
        selc = g_selc1; selv = g_selv1; sumexp = g_sum1;
    } else {
        xo = x - 392; B = w2P; bias = b2; N = 50000; KT = 1; aoff = 20;
        selc = g_selc2; selv = g_selv2; sumexp = g_sum2;
    }
    const int bm = blockIdx.y * 128;
    const int bn = xo * 128;

    if (tid == 0) {
        #pragma unroll
        for (int s = 0; s < NSTAGE; s++) MBARRIER_INIT(sb + s * 8, 1);
    }
    {
        int gc = bn + tid;
        biasS[tid] = (gc < N) ? bias[gc] : 0.f;
    }
    __syncthreads();

    AccTile T;
    gemm_mainloop(T, dsm, sb, hpAll + (size_t)aoff * SLAB_ELEMS, B,
                  blockIdx.y, xo, 22, KT, KT, tid, wm, wn);

    // epilogue: per-warp 64x68 staging overlaid on slab smem (all copies consumed)
    float* Cw = reinterpret_cast<float*>(dsm + 1024 + warp * 17408);
    #pragma unroll
    for (int fm = 0; fm < 4; fm++)
        #pragma unroll
        for (int fn = 0; fn < 4; fn++)
            wmma::store_matrix_sync(&Cw[(fm * 16) * 68 + fn * 16], T.a[fm][fn], 68,
                                    wmma::mem_row_major);
    __syncwarp();

    #pragma unroll
    for (int i = 0; i < 2; i++) {
        int r  = lane + i * 32;                    // 0..63 within warp's row block
        int gr = bm + wm * 64 + r;
        int sc = selc[gr];
        float rowsum = 0.f;
        #pragma unroll 8
        for (int c = 0; c < 64; c++) {
            int col128 = wn * 64 + c;
            int gc = bn + col128;
            if (gc < N) {
                float lg = Cw[r * 68 + c] + biasS[col128];
                rowsum += __expf(lg);
                if (gc == sc) selv[gr] = lg;
            }
        }
        atomicAdd(&sumexp[gr], rowsum);
    }
}

// ================= projection GEMM (unfused, packed bf16 out) =================
__global__ void __launch_bounds__(128, 2)
k_proj(const __nv_bfloat16* __restrict__ A,
       const __nv_bfloat16* __restrict__ B,
       __nv_bfloat16* __restrict__ Cp)
{
    extern __shared__ __align__(128) char dsm[];
    const uint32_t sb = smem_u32(dsm);
    const int tid  = threadIdx.x;
    const int warp = tid >> 5;
    const int lane = tid & 31;
    const int wm   = warp >> 1;
    const int wn   = warp & 1;
    const int bm   = blockIdx.y * 128;
    const int bn   = blockIdx.x * 128;

    if (tid == 0) {
        #pragma unroll
        for (int s = 0; s < NSTAGE; s++) MBARRIER_INIT(sb + s * 8, 1);
    }
    __syncthreads();

    AccTile T;
    gemm_mainloop(T, dsm, sb, A, B, blockIdx.y, blockIdx.x, 16, 16, 16, tid, wm, wn);

    float* Cw = reinterpret_cast<float*>(dsm + 1024 + warp * 17408);
    #pragma unroll
    for (int fm = 0; fm < 4; fm++)
        #pragma unroll
        for (int fn = 0; fn < 4; fn++)
            wmma::store_matrix_sync(&Cw[(fm * 16) * 68 + fn * 16], T.a[fm][fn], 68,
                                    wmma::mem_row_major);
    __syncwarp();

    #pragma unroll
    for (int i = 0; i < 2; i++) {
        int r  = lane + i * 32;
        int gr = bm + wm * 64 + r;
        #pragma unroll 8
        for (int c = 0; c < 64; c++) {
            int gc = bn + wn * 64 + c;
            if (gc < 1408) {
                size_t doff = ((size_t)(gr >> 7) * 22 + (gc >> 6)) * SLAB_ELEMS
                              + (size_t)(gr & 127) * 72 + (gc & 63);
                Cp[doff] = __float2bfloat16(Cw[r * 68 + c]);
            }
        }
    }
}

// ================= cluster logits (head cols 20000, 20001); hp0 = hpAll slabs 0..15 =======
__global__ void k_cluster(const __nv_bfloat16* __restrict__ hpAll,
                          const float* __restrict__ cw,
                          const float* __restrict__ cb)
{
    int row  = blockIdx.x * 8 + (threadIdx.x >> 5);
    int lane = threadIdx.x & 31;
    if (row >= NROWS) return;
    size_t rbase = (size_t)(row >> 7) * 22 * SLAB_ELEMS + (size_t)(row & 127) * 72;
    float s0 = 0.f, s1 = 0.f;
    for (int k = lane; k < DIM; k += 32) {
        float h = __bfloat162float(hpAll[rbase + (size_t)(k >> 6) * SLAB_ELEMS + (k & 63)]);
        s0 += h * cw[k];
        s1 += h * cw[DIM + k];
    }
    #pragma unroll
    for (int o = 16; o > 0; o >>= 1) {
        s0 += __shfl_xor_sync(0xffffffffu, s0, o);
        s1 += __shfl_xor_sync(0xffffffffu, s1, o);
    }
    if (lane == 0) {
        float c0 = s0 + cb[0];
        float c1 = s1 + cb[1];
        atomicAdd(&g_sum0[row], __expf(c0) + __expf(c1));
        int t = g_tgt[row];
        // reference quirk head_lp[:, -i]: tail1 -> col 20001 (c1); tail2 -> col 20000 (c0)
        if (t >= 50000)      g_selh[row] = c0;
        else if (t >= 20000) g_selh[row] = c1;
    }
}

// ================= finalize =================
__global__ void k_final(float* __restrict__ out) {
    int r = blockIdx.x * blockDim.x + threadIdx.x;
    if (r >= NROWS) return;
    int t = g_tgt[r];
    float lse0 = logf(g_sum0[r]);
    float nll;
    if (t < 20000)
        nll = -(g_selh[r] - lse0);
    else if (t < 50000)
        nll = -((g_selh[r] - lse0) + (g_selv1[r] - logf(g_sum1[r])));
    else
        nll = -((g_selh[r] - lse0) + (g_selv2[r] - logf(g_sum2[r])));
    out[r] = nll;
}

// ================= launch =================
static inline void* sym(const void* s) {
    void* p = nullptr;
    cudaGetSymbolAddress(&p, s);
    return p;
}

extern "C" void kernel_launch(void* const* d_in, const int* in_sizes, int n_in,
                              void* d_out, int out_size)
{
    const float* hidden = (const float*)d_in[0];
    const int*   target = (const int*)d_in[1];
    const float* w0     = (const float*)d_in[2];
    const float* b0     = (const float*)d_in[3];
    const float* cw     = (const float*)d_in[4];
    const float* cb     = (const float*)d_in[5];
    const float* p0     = (const float*)d_in[6];
    const float* w1     = (const float*)d_in[7];
    const float* b1     = (const float*)d_in[8];
    const float* p1     = (const float*)d_in[9];
    const float* w2     = (const float*)d_in[10];
    const float* b2     = (const float*)d_in[11];
    const float* p2     = (const float*)d_in[12];
    float* out = (float*)d_out;

    __nv_bfloat16* hP    = (__nv_bfloat16*)sym(g_hP);
    __nv_bfloat16* pT    = (__nv_bfloat16*)sym(g_pT);
    __nv_bfloat16* w0P   = (__nv_bfloat16*)sym(g_w0P);
    __nv_bfloat16* w1P   = (__nv_bfloat16*)sym(g_w1P);
    __nv_bfloat16* w2P   = (__nv_bfloat16*)sym(g_w2P);
    __nv_bfloat16* hpAll = (__nv_bfloat16*)sym(g_hpAll);

    const int SMEM_WM = 1024 + NSTAGE * 2 * SLAB_BYTES;   // 111616 (2 CTAs/SM)
    cudaFuncSetAttribute(k_logit, cudaFuncAttributeMaxDynamicSharedMemorySize, SMEM_WM);
    cudaFuncSetAttribute(k_proj,  cudaFuncAttributeMaxDynamicSharedMemorySize, SMEM_WM);

    // 0: all row-major packs (h, w0, w1, w2)
    k_packAll<<<dim3(8, 391, 4), 256>>>(hidden, hP, w0, w0P, w1, w1P, w2, w2P);
    // 1: transpose-pack p0|p1|p2 + target decode/init
    k_packT_init<<<dim3(45, 32), dim3(32, 8)>>>(p0, p1, p2, pT, target);
    // 2: fused projection GEMM -> hpAll [2048, 1408 packed, ldC=22]
    k_proj<<<dim3(11, 16), 128, SMEM_WM>>>(hP, pT, hpAll);
    // 3: MERGED logit GEMM (head + tail1 + tail2)
    k_logit<<<dim3(157 + 235 + 391, 16), 128, SMEM_WM>>>(hpAll, w0P, b0, w1P, b1, w2P, b2);
    // 4: cluster logits
    k_cluster<<<NROWS / 8, 256>>>(hpAll, cw, cb);
    // 5: finalize
    k_final<<<(NROWS + 255) / 256, 256>>>(out);
}

// round 14
// speedup vs baseline: 1.0000x; 1.0000x over previous
#include <cuda_runtime.h>
#include <cuda_bf16.h>
#include <mma.h>
#include <cstdint>

using namespace nvcuda;

#define NROWS 2048
#define DIM   1024

// Packed slab layout: matrix [Rpad, K] (K-major) stored as 128-row x 64-K slabs.
// Slab (rt, kt) at ((rt*ld)+kt)*SLAB_ELEMS; row r at r*72 elems (144B stride), col c at +c.
#define SLAB_ELEMS 9216
#define SLAB_BYTES 18432
#define NSTAGE 3
// GEMM stage = A(2 slabs, 256 rows) + B(1 slab) = 55296 B
#define STAGE_BYTES (3 * SLAB_BYTES)

// ================= helpers =================
__device__ __forceinline__ uint32_t smem_u32(const void* p) {
    uint32_t a;
    asm("{ .reg .u64 t; cvta.to.shared.u64 t, %1; cvt.u32.u64 %0, t; }" : "=r"(a) : "l"(p));
    return a;
}
#define MBARRIER_INIT(mbar, cnt) \
    asm volatile("mbarrier.init.shared.b64 [%0], %1;" \
                 :: "r"((uint32_t)(mbar)), "r"((uint32_t)(cnt)) : "memory")
#define MBARRIER_EXPECT_TX(mbar, tx) \
    asm volatile("mbarrier.arrive.expect_tx.shared.b64 _, [%0], %1;" \
                 :: "r"((uint32_t)(mbar)), "r"((uint32_t)(tx)) : "memory")
#define MBARRIER_WAIT_PARITY(mbar, par) do { \
    uint32_t _m = (uint32_t)(mbar); uint32_t _p = (uint32_t)(par); uint32_t _d; \
    asm volatile("{\n\t.reg .pred p;\n\t" \
        "mbarrier.try_wait.parity.acquire.cta.shared::cta.b64 p, [%1], %2;\n\t" \
        "selp.b32 %0, 1, 0, p;\n\t}" : "=r"(_d) : "r"(_m), "r"(_p) : "memory"); \
    if (!_d) { \
        asm volatile("{\n\t.reg .pred P1;\n\t" \
            "WL_%=:\n\t" \
            "mbarrier.try_wait.parity.acquire.cta.shared::cta.b64 P1, [%0], %1, 0x989680;\n\t" \
            "@P1 bra.uni WD_%=;\n\t" \
            "bra.uni WL_%=;\n\t" \
            "WD_%=:\n\t}" :: "r"(_m), "r"(_p) : "memory"); \
    } \
} while (0)
__device__ __forceinline__ void bulk_g2s(uint32_t dst, const void* src, uint32_t bytes,
                                         uint32_t mbar) {
    asm volatile(
        "cp.async.bulk.shared::cluster.global.mbarrier::complete_tx::bytes [%0], [%1], %2, [%3];"
        :: "r"(dst), "l"(src), "r"(bytes), "r"(mbar) : "memory");
}

// ================= packed scratch buffers (bf16) =================
__device__ __align__(256) __nv_bfloat16 g_hP   [16 * 16 * SLAB_ELEMS];   // h [2048,1024]
__device__ __align__(256) __nv_bfloat16 g_pT   [11 * 16 * SLAB_ELEMS];   // projT cat [1408,1024]
__device__ __align__(256) __nv_bfloat16 g_w0P  [157 * 16 * SLAB_ELEMS];
__device__ __align__(256) __nv_bfloat16 g_w1P  [235 *  4 * SLAB_ELEMS];
__device__ __align__(256) __nv_bfloat16 g_w2P  [391 *  1 * SLAB_ELEMS];
__device__ __align__(256) __nv_bfloat16 g_hpAll[16 * 22 * SLAB_ELEMS];   // hp cat [2048,1408]
__device__ __align__(256) float g_sum0[NROWS];
__device__ __align__(256) float g_sum1[NROWS];
__device__ __align__(256) float g_sum2[NROWS];
__device__ __align__(256) float g_selh [NROWS];
__device__ __align__(256) float g_selv1[NROWS];
__device__ __align__(256) float g_selv2[NROWS];
__device__ __align__(256) int   g_selc0[NROWS];
__device__ __align__(256) int   g_selc1[NROWS];
__device__ __align__(256) int   g_selc2[NROWS];
__device__ __align__(256) int   g_tgt  [NROWS];

// ======== packAll: 4 row-major fp32 matrices -> packed bf16 slabs in ONE launch ==========
__global__ void k_packAll(const float* __restrict__ h,  __nv_bfloat16* __restrict__ hP,
                          const float* __restrict__ w0, __nv_bfloat16* __restrict__ w0P,
                          const float* __restrict__ w1, __nv_bfloat16* __restrict__ w1P,
                          const float* __restrict__ w2, __nv_bfloat16* __restrict__ w2P)
{
    const float* src; __nv_bfloat16* dst; int R, K, tiles;
    switch (blockIdx.z) {
        case 0: src = h;  dst = hP;  R = 2048;  K = 1024; tiles = 16;  break;
        case 1: src = w0; dst = w0P; R = 20000; K = 1024; tiles = 157; break;
        case 2: src = w1; dst = w1P; R = 30000; K = 256;  tiles = 235; break;
        default:src = w2; dst = w2P; R = 50000; K = 64;   tiles = 391; break;
    }
    if ((int)blockIdx.y >= tiles) return;
    int chunksPerRow = K >> 3;
    int shift = 31 - __clz(chunksPerRow);
    int blockChunks = chunksPerRow << 7;
    int rbase = blockIdx.y << 7;
    for (int idx = blockIdx.x * blockDim.x + threadIdx.x; idx < blockChunks;
         idx += gridDim.x * blockDim.x) {
        int rloc = idx >> shift;
        int c    = idx & (chunksPerRow - 1);
        int r    = rbase + rloc;
        int kt = c >> 3, ci = c & 7;
        size_t doff = ((size_t)blockIdx.y * (K >> 6) + kt) * SLAB_ELEMS
                      + (size_t)rloc * 72 + ci * 8;
        uint4 o = make_uint4(0u, 0u, 0u, 0u);
        if (r < R) {
            const float4* s = reinterpret_cast<const float4*>(src + (size_t)r * K + c * 8);
            float4 v0 = s[0], v1 = s[1];
            __nv_bfloat162 b0 = __floats2bfloat162_rn(v0.x, v0.y);
            __nv_bfloat162 b1 = __floats2bfloat162_rn(v0.z, v0.w);
            __nv_bfloat162 b2 = __floats2bfloat162_rn(v1.x, v1.y);
            __nv_bfloat162 b3 = __floats2bfloat162_rn(v1.z, v1.w);
            o.x = *reinterpret_cast<uint32_t*>(&b0);
            o.y = *reinterpret_cast<uint32_t*>(&b1);
            o.z = *reinterpret_cast<uint32_t*>(&b2);
            o.w = *reinterpret_cast<uint32_t*>(&b3);
        }
        *reinterpret_cast<uint4*>(dst + doff) = o;
    }
}

// ======== packT_init: transpose-pack p0|p1|p2 -> g_pT [1408,1024] + target decode =========
__global__ void k_packT_init(const float* __restrict__ p0, const float* __restrict__ p1,
                             const float* __restrict__ p2, __nv_bfloat16* __restrict__ pT,
                             const int* __restrict__ t32)
{
    if (blockIdx.x == 44) {
        if (blockIdx.y != 0) return;
        int tid = threadIdx.y * 32 + threadIdx.x;
        __shared__ int s_nonzero_odd;
        if (tid == 0) s_nonzero_odd = 0;
        __syncthreads();
        for (int i = tid; i < NROWS / 2; i += 256)
            if (t32[2 * i + 1] != 0) atomicOr(&s_nonzero_odd, 1);
        __syncthreads();
        bool is64 = (s_nonzero_odd == 0);
        for (int r = tid; r < NROWS; r += 256) {
            int t = is64 ? t32[2 * r] : t32[r];
            g_tgt[r] = t;
            g_sum0[r] = 0.f; g_sum1[r] = 0.f; g_sum2[r] = 0.f;
            g_selc0[r] = (t < 20000) ? t : -1;
            int t1 = t - 20000; if (t1 < 0) t1 = 0; if (t1 > 29999) t1 = 29999;
            g_selc1[r] = t1;
            int t2 = t - 50000; if (t2 < 0) t2 = 0; if (t2 > 49999) t2 = 49999;
            g_selc2[r] = t2;
        }
        return;
    }
    __shared__ float t[32][33];
    int n0 = blockIdx.x * 32, k0 = blockIdx.y * 32;
    int x = threadIdx.x, y = threadIdx.y;
    #pragma unroll
    for (int i = 0; i < 32; i += 8) {
        int k = k0 + y + i, n = n0 + x;
        float v;
        if (n < 1024)       v = p0[(size_t)k * 1024 + n];
        else if (n < 1280)  v = p1[(size_t)k * 256 + (n - 1024)];
        else if (n < 1344)  v = p2[(size_t)k * 64 + (n - 1280)];
        else                v = 0.f;
        t[y + i][x] = v;
    }
    __syncthreads();
    #pragma unroll
    for (int i = 0; i < 32; i += 8) {
        int n = n0 + y + i, k = k0 + x;
        size_t doff = ((size_t)(n >> 7) * 16 + (k >> 6)) * SLAB_ELEMS
                      + (size_t)(n & 127) * 72 + (k & 63);
        pT[doff] = __float2bfloat16(t[x][y + i]);
    }
}

// ========== shared GEMM mainloop: 256x128 block tile, 16 warps (8m x 2n), 32x64/warp ======
// acc = A_tile(256 rows) @ B_tile(128 rows)^T over KT 64-K slabs. 512 threads, 1 CTA/SM.
struct AccTile {
    wmma::fragment<wmma::accumulator, 16, 16, 16, float> a[2][4];
};
__device__ __forceinline__ void gemm_mainloop(
    AccTile& T, char* dsm, uint32_t sb,
    const __nv_bfloat16* A, const __nv_bfloat16* B,
    int rowTile2, int colTile, int ldA, int ldB, int KT,
    int tid, int wm, int wn)
{
    auto stage = [&](int s) { return dsm + 1024 + s * STAGE_BYTES; };
    auto issue = [&](int kt, int s) {
        uint32_t mb = sb + (uint32_t)s * 8;
        MBARRIER_EXPECT_TX(mb, STAGE_BYTES);
        const char* a0 = reinterpret_cast<const char*>(A)
                         + ((size_t)(rowTile2 * 2) * ldA + kt) * SLAB_BYTES;
        const char* a1 = reinterpret_cast<const char*>(A)
                         + ((size_t)(rowTile2 * 2 + 1) * ldA + kt) * SLAB_BYTES;
        const char* bS = reinterpret_cast<const char*>(B)
                         + ((size_t)colTile * ldB + kt) * SLAB_BYTES;
        uint32_t d = smem_u32(stage(s));
        bulk_g2s(d,                  a0, SLAB_BYTES, mb);
        bulk_g2s(d + SLAB_BYTES,     a1, SLAB_BYTES, mb);
        bulk_g2s(d + 2 * SLAB_BYTES, bS, SLAB_BYTES, mb);
    };
    if (tid == 0) {
        #pragma unroll
        for (int s = 0; s < NSTAGE; s++)
            if (s < KT) issue(s, s);
    }

    #pragma unroll
    for (int fm = 0; fm < 2; fm++)
        #pragma unroll
        for (int fn = 0; fn < 4; fn++)
            wmma::fill_fragment(T.a[fm][fn], 0.f);

    // this warp's A rows: wm*32 .. wm*32+31 -> chunk (wm>=4), local row
    const int rbase = wm * 32;
    const int aChunkOff = (rbase >> 7) * SLAB_ELEMS;   // 0 or SLAB_ELEMS
    const int rloc = rbase & 127;

    int s = 0, ph = 0;
    for (int kt = 0; kt < KT; kt++) {
        MBARRIER_WAIT_PARITY(sb + (uint32_t)s * 8, ph);
        const __nv_bfloat16* As = reinterpret_cast<const __nv_bfloat16*>(stage(s)) + aChunkOff;
        const __nv_bfloat16* Bs = reinterpret_cast<const __nv_bfloat16*>(stage(s) + 2 * SLAB_BYTES);
        #pragma unroll
        for (int kk = 0; kk < 64; kk += 16) {
            wmma::fragment<wmma::matrix_a, 16, 16, 16, __nv_bfloat16, wmma::row_major> af[2];
            #pragma unroll
            for (int fm = 0; fm < 2; fm++)
                wmma::load_matrix_sync(af[fm], As + (rloc + fm * 16) * 72 + kk, 72);
            #pragma unroll
            for (int fn = 0; fn < 4; fn++) {
                wmma::fragment<wmma::matrix_b, 16, 16, 16, __nv_bfloat16, wmma::col_major> bf;
                wmma::load_matrix_sync(bf, Bs + (wn * 64 + fn * 16) * 72 + kk, 72);
                #pragma unroll
                for (int fm = 0; fm < 2; fm++)
                    wmma::mma_sync(T.a[fm][fn], af[fm], bf, T.a[fm][fn]);
            }
        }
        __syncthreads();   // stage s consumed by all warps
        if (tid == 0 && kt + NSTAGE < KT) issue(kt + NSTAGE, s);
        if (++s == NSTAGE) { s = 0; ph ^= 1; }
    }
}

// ================= merged logit GEMM: head + tail1 + tail2 in ONE launch =================
// grid (157+235+391, 8), 512 threads. Segment from blockIdx.x. Fused exp epilogue.
__global__ void __launch_bounds__(512, 1)
k_logit(const __nv_bfloat16* __restrict__ hpAll,
        const __nv_bfloat16* __restrict__ w0P, const float* __restrict__ b0,
        const __nv_bfloat16* __restrict__ w1P, const float* __restrict__ b1,
        const __nv_bfloat16* __restrict__ w2P, const float* __restrict__ b2)
{
    extern __shared__ __align__(128) char dsm[];
    const uint32_t sb = smem_u32(dsm);
    float* biasS = reinterpret_cast<float*>(dsm + 64);

    const int tid  = threadIdx.x;
    const int warp = tid >> 5;
    const int lane = tid & 31;
    const int wm   = warp >> 1;   // 0..7 -> rows wm*32
    const int wn   = warp & 1;    // 0..1 -> cols wn*64

    int x = blockIdx.x;
    int xo;
    const __nv_bfloat16* B; const float* bias;
    const int* selc; float* selv; float* sumexp;
    int N, KT, aoff;
    if (x < 157) {
        xo = x; B = w0P; bias = b0; N = 20000; KT = 16; aoff = 0;
        selc = g_selc0; selv = g_selh; sumexp = g_sum0;
    } else if (x < 392) {
        xo = x - 157; B = w1P; bias = b1; N = 30000; KT = 4; aoff = 16;
        selc = g_selc1; selv = g_selv1; sumexp = g_sum1;
    } else {
        xo = x - 392; B = w2P; bias = b2; N = 50000; KT = 1; aoff = 20;
        selc = g_selc2; selv = g_selv2; sumexp = g_sum2;
    }
    const int bm = blockIdx.y * 256;
    const int bn = xo * 128;

    if (tid == 0) {
        #pragma unroll
        for (int s = 0; s < NSTAGE; s++) MBARRIER_INIT(sb + s * 8, 1);
    }
    if (tid < 128) {
        int gc = bn + tid;
        biasS[tid] = (gc < N) ? bias[gc] : 0.f;
    }
    __syncthreads();

    AccTile T;
    gemm_mainloop(T, dsm, sb, hpAll + (size_t)aoff * SLAB_ELEMS, B,
                  blockIdx.y, xo, 22, KT, KT, tid, wm, wn);

    // epilogue: per-warp 32x68 staging overlaid on stage smem (all copies consumed)
    float* Cw = reinterpret_cast<float*>(dsm + 1024 + warp * 8704);
    #pragma unroll
    for (int fm = 0; fm < 2; fm++)
        #pragma unroll
        for (int fn = 0; fn < 4; fn++)
            wmma::store_matrix_sync(&Cw[(fm * 16) * 68 + fn * 16], T.a[fm][fn], 68,
                                    wmma::mem_row_major);
    __syncwarp();

    int r  = lane;
    int gr = bm + wm * 32 + r;
    int sc = selc[gr];
    float rowsum = 0.f;
    #pragma unroll 8
    for (int c = 0; c < 64; c++) {
        int col128 = wn * 64 + c;
        int gc = bn + col128;
        if (gc < N) {
            float lg = Cw[r * 68 + c] + biasS[col128];
            rowsum += __expf(lg);
            if (gc == sc) selv[gr] = lg;
        }
    }
    atomicAdd(&sumexp[gr], rowsum);
}

// ================= projection GEMM (unfused, packed bf16 out) =================
__global__ void __launch_bounds__(512, 1)
k_proj(const __nv_bfloat16* __restrict__ A,
       const __nv_bfloat16* __restrict__ B,
       __nv_bfloat16* __restrict__ Cp)
{
    extern __shared__ __align__(128) char dsm[];
    const uint32_t sb = smem_u32(dsm);
    const int tid  = threadIdx.x;
    const int warp = tid >> 5;
    const int lane = tid & 31;
    const int wm   = warp >> 1;
    const int wn   = warp & 1;
    const int bm   = blockIdx.y * 256;
    const int bn   = blockIdx.x * 128;

    if (tid == 0) {
        #pragma unroll
        for (int s = 0; s < NSTAGE; s++) MBARRIER_INIT(sb + s * 8, 1);
    }
    __syncthreads();

    AccTile T;
    gemm_mainloop(T, dsm, sb, A, B, blockIdx.y, blockIdx.x, 16, 16, 16, tid, wm, wn);

    float* Cw = reinterpret_cast<float*>(dsm + 1024 + warp * 8704);
    #pragma unroll
    for (int fm = 0; fm < 2; fm++)
        #pragma unroll
        for (int fn = 0; fn < 4; fn++)
            wmma::store_matrix_sync(&Cw[(fm * 16) * 68 + fn * 16], T.a[fm][fn], 68,
                                    wmma::mem_row_major);
    __syncwarp();

    int r  = lane;
    int gr = bm + wm * 32 + r;
    #pragma unroll 8
    for (int c = 0; c < 64; c++) {
        int gc = bn + wn * 64 + c;
        if (gc < 1408) {
            size_t doff = ((size_t)(gr >> 7) * 22 + (gc >> 6)) * SLAB_ELEMS
                          + (size_t)(gr & 127) * 72 + (gc & 63);
            Cp[doff] = __float2bfloat16(Cw[r * 68 + c]);
        }
    }
}

// ================= cluster logits (head cols 20000, 20001); hp0 = hpAll slabs 0..15 =======
__global__ void k_cluster(const __nv_bfloat16* __restrict__ hpAll,
                          const float* __restrict__ cw,
                          const float* __restrict__ cb)
{
    int row  = blockIdx.x * 8 + (threadIdx.x >> 5);
    int lane = threadIdx.x & 31;
    if (row >= NROWS) return;
    size_t rbase = (size_t)(row >> 7) * 22 * SLAB_ELEMS + (size_t)(row & 127) * 72;
    float s0 = 0.f, s1 = 0.f;
    for (int k = lane; k < DIM; k += 32) {
        float h = __bfloat162float(hpAll[rbase + (size_t)(k >> 6) * SLAB_ELEMS + (k & 63)]);
        s0 += h * cw[k];
        s1 += h * cw[DIM + k];
    }
    #pragma unroll
    for (int o = 16; o > 0; o >>= 1) {
        s0 += __shfl_xor_sync(0xffffffffu, s0, o);
        s1 += __shfl_xor_sync(0xffffffffu, s1, o);
    }
    if (lane == 0) {
        float c0 = s0 + cb[0];
        float c1 = s1 + cb[1];
        atomicAdd(&g_sum0[row], __expf(c0) + __expf(c1));
        int t = g_tgt[row];
        // reference quirk head_lp[:, -i]: tail1 -> col 20001 (c1); tail2 -> col 20000 (c0)
        if (t >= 50000)      g_selh[row] = c0;
        else if (t >= 20000) g_selh[row] = c1;
    }
}

// ================= finalize =================
__global__ void k_final(float* __restrict__ out) {
    int r = blockIdx.x * blockDim.x + threadIdx.x;
    if (r >= NROWS) return;
    int t = g_tgt[r];
    float lse0 = logf(g_sum0[r]);
    float nll;
    if (t < 20000)
        nll = -(g_selh[r] - lse0);
    else if (t < 50000)
        nll = -((g_selh[r] - lse0) + (g_selv1[r] - logf(g_sum1[r])));
    else
        nll = -((g_selh[r] - lse0) + (g_selv2[r] - logf(g_sum2[r])));
    out[r] = nll;
}

// ================= launch =================
static inline void* sym(const void* s) {
    void* p = nullptr;
    cudaGetSymbolAddress(&p, s);
    return p;
}

extern "C" void kernel_launch(void* const* d_in, const int* in_sizes, int n_in,
                              void* d_out, int out_size)
{
    const float* hidden = (const float*)d_in[0];
    const int*   target = (const int*)d_in[1];
    const float* w0     = (const float*)d_in[2];
    const float* b0     = (const float*)d_in[3];
    const float* cw     = (const float*)d_in[4];
    const float* cb     = (const float*)d_in[5];
    const float* p0     = (const float*)d_in[6];
    const float* w1     = (const float*)d_in[7];
    const float* b1     = (const float*)d_in[8];
    const float* p1     = (const float*)d_in[9];
    const float* w2     = (const float*)d_in[10];
    const float* b2     = (const float*)d_in[11];
    const float* p2     = (const float*)d_in[12];
    float* out = (float*)d_out;

    __nv_bfloat16* hP    = (__nv_bfloat16*)sym(g_hP);
    __nv_bfloat16* pT    = (__nv_bfloat16*)sym(g_pT);
    __nv_bfloat16* w0P   = (__nv_bfloat16*)sym(g_w0P);
    __nv_bfloat16* w1P   = (__nv_bfloat16*)sym(g_w1P);
    __nv_bfloat16* w2P   = (__nv_bfloat16*)sym(g_w2P);
    __nv_bfloat16* hpAll = (__nv_bfloat16*)sym(g_hpAll);

    const int SMEM_WM = 1024 + NSTAGE * STAGE_BYTES;   // 166912 (1 CTA/SM, 16 warps)
    cudaFuncSetAttribute(k_logit, cudaFuncAttributeMaxDynamicSharedMemorySize, SMEM_WM);
    cudaFuncSetAttribute(k_proj,  cudaFuncAttributeMaxDynamicSharedMemorySize, SMEM_WM);

    // 0: all row-major packs (h, w0, w1, w2)
    k_packAll<<<dim3(8, 391, 4), 256>>>(hidden, hP, w0, w0P, w1, w1P, w2, w2P);
    // 1: transpose-pack p0|p1|p2 + target decode/init
    k_packT_init<<<dim3(45, 32), dim3(32, 8)>>>(p0, p1, p2, pT, target);
    // 2: fused projection GEMM -> hpAll [2048, 1408 packed, ldC=22]
    k_proj<<<dim3(11, 8), 512, SMEM_WM>>>(hP, pT, hpAll);
    // 3: MERGED logit GEMM (head + tail1 + tail2)
    k_logit<<<dim3(157 + 235 + 391, 8), 512, SMEM_WM>>>(hpAll, w0P, b0, w1P, b1, w2P, b2);
    // 4: cluster logits
    k_cluster<<<NROWS / 8, 256>>>(hpAll, cw, cb);
    // 5: finalize
    k_final<<<(NROWS + 255) / 256, 256>>>(out);
}

// round 15
// speedup vs baseline: 1.4763x; 1.4762x over previous
#include <cuda_runtime.h>
#include <cuda_bf16.h>
#include <mma.h>
#include <cstdint>

using namespace nvcuda;

#define NROWS 2048
#define DIM   1024

// Packed slab layout: matrix [Rpad, K] (K-major) stored as slabs of 128 rows x 64 K.
// Within a row-tile rt, slab kt lives at ((rt*ld)+kt)*SLAB_ELEMS (ld = slabs per row-tile).
// Row r at r*72 elems (144B stride), col c at +c. Slab = 18432B contiguous -> one bulk copy.
#define SLAB_ELEMS 9216
#define SLAB_BYTES 18432

// ================= helpers =================
__device__ __forceinline__ uint32_t smem_u32(const void* p) {
    uint32_t a;
    asm("{ .reg .u64 t; cvta.to.shared.u64 t, %1; cvt.u32.u64 %0, t; }" : "=r"(a) : "l"(p));
    return a;
}
#define MBARRIER_INIT(mbar, cnt) \
    asm volatile("mbarrier.init.shared.b64 [%0], %1;" \
                 :: "r"((uint32_t)(mbar)), "r"((uint32_t)(cnt)) : "memory")
#define MBARRIER_EXPECT_TX(mbar, tx) \
    asm volatile("mbarrier.arrive.expect_tx.shared.b64 _, [%0], %1;" \
                 :: "r"((uint32_t)(mbar)), "r"((uint32_t)(tx)) : "memory")
#define MBARRIER_WAIT_PARITY(mbar, par) do { \
    uint32_t _m = (uint32_t)(mbar); uint32_t _p = (uint32_t)(par); uint32_t _d; \
    asm volatile("{\n\t.reg .pred p;\n\t" \
        "mbarrier.try_wait.parity.acquire.cta.shared::cta.b64 p, [%1], %2;\n\t" \
        "selp.b32 %0, 1, 0, p;\n\t}" : "=r"(_d) : "r"(_m), "r"(_p) : "memory"); \
    if (!_d) { \
        asm volatile("{\n\t.reg .pred P1;\n\t" \
            "WL_%=:\n\t" \
            "mbarrier.try_wait.parity.acquire.cta.shared::cta.b64 P1, [%0], %1, 0x989680;\n\t" \
            "@P1 bra.uni WD_%=;\n\t" \
            "bra.uni WL_%=;\n\t" \
            "WD_%=:\n\t}" :: "r"(_m), "r"(_p) : "memory"); \
    } \
} while (0)
__device__ __forceinline__ void bulk_g2s(uint32_t dst, const void* src, uint32_t bytes,
                                         uint32_t mbar) {
    asm volatile(
        "cp.async.bulk.shared::cluster.global.mbarrier::complete_tx::bytes [%0], [%1], %2, [%3];"
        :: "r"(dst), "l"(src), "r"(bytes), "r"(mbar) : "memory");
}

// ================= packed scratch buffers (bf16) =================
__device__ __align__(256) __nv_bfloat16 g_hP   [16 * 16 * SLAB_ELEMS];   // h [2048,1024]
__device__ __align__(256) __nv_bfloat16 g_pT   [11 * 16 * SLAB_ELEMS];   // projT cat [1408,1024]
__device__ __align__(256) __nv_bfloat16 g_w0P  [157 * 16 * SLAB_ELEMS];
__device__ __align__(256) __nv_bfloat16 g_w1P  [235 *  4 * SLAB_ELEMS];
__device__ __align__(256) __nv_bfloat16 g_w2P  [391 *  1 * SLAB_ELEMS];
__device__ __align__(256) __nv_bfloat16 g_hpAll[16 * 22 * SLAB_ELEMS];   // hp cat [2048,1408]
__device__ __align__(256) __nv_bfloat16 g_hp1C [16 *  4 * SLAB_ELEMS];   // compacted tail1 rows
__device__ __align__(256) __nv_bfloat16 g_hp2C [16 *  1 * SLAB_ELEMS];   // compacted tail2 rows
__device__ __align__(256) float g_sum0[NROWS];
__device__ __align__(256) float g_sum1[NROWS];
__device__ __align__(256) float g_sum2[NROWS];
__device__ __align__(256) float g_selh [NROWS];
__device__ __align__(256) float g_selv1[NROWS];
__device__ __align__(256) float g_selv2[NROWS];
__device__ __align__(256) int   g_selc0[NROWS];
__device__ __align__(256) int   g_selc1[NROWS];
__device__ __align__(256) int   g_selc2[NROWS];
__device__ __align__(256) int   g_tgt  [NROWS];
__device__ __align__(256) int   g_rows1[NROWS];   // compacted row lists (-1 pad)
__device__ __align__(256) int   g_rows2[NROWS];
__device__ __align__(256) int   g_cnt[2];         // padded tile counts for tail1/tail2

// ======== packAll: 4 row-major fp32 matrices -> packed bf16 slabs in ONE launch ==========
__global__ void k_packAll(const float* __restrict__ h,  __nv_bfloat16* __restrict__ hP,
                          const float* __restrict__ w0, __nv_bfloat16* __restrict__ w0P,
                          const float* __restrict__ w1, __nv_bfloat16* __restrict__ w1P,
                          const float* __restrict__ w2, __nv_bfloat16* __restrict__ w2P)
{
    const float* src; __nv_bfloat16* dst; int R, K, tiles;
    switch (blockIdx.z) {
        case 0: src = h;  dst = hP;  R = 2048;  K = 1024; tiles = 16;  break;
        case 1: src = w0; dst = w0P; R = 20000; K = 1024; tiles = 157; break;
        case 2: src = w1; dst = w1P; R = 30000; K = 256;  tiles = 235; break;
        default:src = w2; dst = w2P; R = 50000; K = 64;   tiles = 391; break;
    }
    if ((int)blockIdx.y >= tiles) return;
    int chunksPerRow = K >> 3;
    int shift = 31 - __clz(chunksPerRow);
    int blockChunks = chunksPerRow << 7;
    int rbase = blockIdx.y << 7;
    for (int idx = blockIdx.x * blockDim.x + threadIdx.x; idx < blockChunks;
         idx += gridDim.x * blockDim.x) {
        int rloc = idx >> shift;
        int c    = idx & (chunksPerRow - 1);
        int r    = rbase + rloc;
        int kt = c >> 3, ci = c & 7;
        size_t doff = ((size_t)blockIdx.y * (K >> 6) + kt) * SLAB_ELEMS
                      + (size_t)rloc * 72 + ci * 8;
        uint4 o = make_uint4(0u, 0u, 0u, 0u);
        if (r < R) {
            const float4* s = reinterpret_cast<const float4*>(src + (size_t)r * K + c * 8);
            float4 v0 = s[0], v1 = s[1];
            __nv_bfloat162 b0 = __floats2bfloat162_rn(v0.x, v0.y);
            __nv_bfloat162 b1 = __floats2bfloat162_rn(v0.z, v0.w);
            __nv_bfloat162 b2 = __floats2bfloat162_rn(v1.x, v1.y);
            __nv_bfloat162 b3 = __floats2bfloat162_rn(v1.z, v1.w);
            o.x = *reinterpret_cast<uint32_t*>(&b0);
            o.y = *reinterpret_cast<uint32_t*>(&b1);
            o.z = *reinterpret_cast<uint32_t*>(&b2);
            o.w = *reinterpret_cast<uint32_t*>(&b3);
        }
        *reinterpret_cast<uint4*>(dst + doff) = o;
    }
}

// ======== packT_init: transpose-pack p0|p1|p2 -> g_pT + target decode + row compaction ====
__global__ void k_packT_init(const float* __restrict__ p0, const float* __restrict__ p1,
                             const float* __restrict__ p2, __nv_bfloat16* __restrict__ pT,
                             const int* __restrict__ t32)
{
    if (blockIdx.x == 44) {
        if (blockIdx.y != 0) return;
        int tid = threadIdx.y * 32 + threadIdx.x;
        __shared__ int s_nonzero_odd, s_c1, s_c2;
        if (tid == 0) { s_nonzero_odd = 0; s_c1 = 0; s_c2 = 0; }
        __syncthreads();
        for (int i = tid; i < NROWS / 2; i += 256)
            if (t32[2 * i + 1] != 0) atomicOr(&s_nonzero_odd, 1);
        __syncthreads();
        bool is64 = (s_nonzero_odd == 0);
        for (int r = tid; r < NROWS; r += 256) {
            int t = is64 ? t32[2 * r] : t32[r];
            g_tgt[r] = t;
            g_sum0[r] = 0.f; g_sum1[r] = 0.f; g_sum2[r] = 0.f;
            g_selc0[r] = (t < 20000) ? t : -1;
            int t1 = t - 20000; if (t1 < 0) t1 = 0; if (t1 > 29999) t1 = 29999;
            g_selc1[r] = t1;
            int t2 = t - 50000; if (t2 < 0) t2 = 0; if (t2 > 49999) t2 = 49999;
            g_selc2[r] = t2;
            if (t >= 20000 && t < 50000) g_rows1[atomicAdd(&s_c1, 1)] = r;
            else if (t >= 50000)         g_rows2[atomicAdd(&s_c2, 1)] = r;
        }
        __syncthreads();
        int c1 = s_c1, c2 = s_c2;
        int p1n = (c1 + 127) & ~127, p2n = (c2 + 127) & ~127;
        for (int i = c1 + tid; i < p1n; i += 256) g_rows1[i] = -1;
        for (int i = c2 + tid; i < p2n; i += 256) g_rows2[i] = -1;
        if (tid == 0) { g_cnt[0] = p1n >> 7; g_cnt[1] = p2n >> 7; }
        return;
    }
    __shared__ float t[32][33];
    int n0 = blockIdx.x * 32, k0 = blockIdx.y * 32;
    int x = threadIdx.x, y = threadIdx.y;
    #pragma unroll
    for (int i = 0; i < 32; i += 8) {
        int k = k0 + y + i, n = n0 + x;
        float v;
        if (n < 1024)       v = p0[(size_t)k * 1024 + n];
        else if (n < 1280)  v = p1[(size_t)k * 256 + (n - 1024)];
        else if (n < 1344)  v = p2[(size_t)k * 64 + (n - 1280)];
        else                v = 0.f;
        t[y + i][x] = v;
    }
    __syncthreads();
    #pragma unroll
    for (int i = 0; i < 32; i += 8) {
        int n = n0 + y + i, k = k0 + x;
        size_t doff = ((size_t)(n >> 7) * 16 + (k >> 6)) * SLAB_ELEMS
                      + (size_t)(n & 127) * 72 + (k & 63);
        pT[doff] = __float2bfloat16(t[x][y + i]);
    }
}

// ======== gather: compact hpAll tail rows into hp1C (K=256) and hp2C (K=64) ==============
// grid (16, 2): y=0 -> tail1, y=1 -> tail2. 256 threads.
__global__ void k_gather(const __nv_bfloat16* __restrict__ hpAll,
                         __nv_bfloat16* __restrict__ hp1C,
                         __nv_bfloat16* __restrict__ hp2C)
{
    int seg = blockIdx.y;
    int tiles = g_cnt[seg];
    int rt = blockIdx.x;
    if (rt >= tiles) return;
    const int* rows = seg == 0 ? g_rows1 : g_rows2;
    __nv_bfloat16* dst = seg == 0 ? hp1C : hp2C;
    int nSlab = seg == 0 ? 4 : 1;      // K/64
    int aoff  = seg == 0 ? 16 : 20;    // slab offset in hpAll row
    // each row has nSlab*8 uint4 chunks (64 elems = 8 chunks per slab)
    int chunksPerRow = nSlab * 8;
    int total = 128 * chunksPerRow;
    for (int idx = threadIdx.x; idx < total; idx += 256) {
        int rloc = idx / chunksPerRow;
        int c    = idx - rloc * chunksPerRow;
        int kt = c >> 3, ci = c & 7;
        int r  = rt * 128 + rloc;
        int orow = rows[r];
        uint4 v = make_uint4(0u, 0u, 0u, 0u);
        if (orow >= 0) {
            size_t soff = ((size_t)(orow >> 7) * 22 + aoff + kt) * SLAB_ELEMS
                          + (size_t)(orow & 127) * 72 + ci * 8;
            v = *reinterpret_cast<const uint4*>(hpAll + soff);
        }
        size_t doff = ((size_t)rt * nSlab + kt) * SLAB_ELEMS
                      + (size_t)rloc * 72 + ci * 8;
        *reinterpret_cast<uint4*>(dst + doff) = v;
    }
}

// ================= shared GEMM mainloop (2-stage bulk pipeline) =================
struct AccTile {
    wmma::fragment<wmma::accumulator, 16, 16, 16, float> a[2][4];
};
__device__ __forceinline__ void gemm_mainloop(
    AccTile& T, char* dsm, uint32_t sb,
    const __nv_bfloat16* A, const __nv_bfloat16* B,
    int rowTile, int colTile, int ldA, int ldB, int KT,
    int tid, int wm, int wn)
{
    auto slabA = [&](int s) {
        return reinterpret_cast<const __nv_bfloat16*>(dsm + 1024 + s * 2 * SLAB_BYTES);
    };
    auto slabB = [&](int s) {
        return reinterpret_cast<const __nv_bfloat16*>(dsm + 1024 + s * 2 * SLAB_BYTES + SLAB_BYTES);
    };
    auto issue = [&](int kt, int s) {
        uint32_t mb = sb + (uint32_t)s * 8;
        MBARRIER_EXPECT_TX(mb, 2 * SLAB_BYTES);
        const char* aS = reinterpret_cast<const char*>(A)
                         + ((size_t)rowTile * ldA + kt) * SLAB_BYTES;
        const char* bS = reinterpret_cast<const char*>(B)
                         + ((size_t)colTile * ldB + kt) * SLAB_BYTES;
        bulk_g2s(smem_u32(slabA(s)), aS, SLAB_BYTES, mb);
        bulk_g2s(smem_u32(slabB(s)), bS, SLAB_BYTES, mb);
    };
    if (tid == 0) { issue(0, 0); if (KT > 1) issue(1, 1); }

    #pragma unroll
    for (int fm = 0; fm < 2; fm++)
        #pragma unroll
        for (int fn = 0; fn < 4; fn++)
            wmma::fill_fragment(T.a[fm][fn], 0.f);

    for (int kt = 0; kt < KT; kt++) {
        int s = kt & 1;
        MBARRIER_WAIT_PARITY(sb + (uint32_t)s * 8, (kt >> 1) & 1);
        const __nv_bfloat16* As = slabA(s);
        const __nv_bfloat16* Bs = slabB(s);
        #pragma unroll
        for (int kk = 0; kk < 64; kk += 16) {
            wmma::fragment<wmma::matrix_a, 16, 16, 16, __nv_bfloat16, wmma::row_major> af[2];
            #pragma unroll
            for (int fm = 0; fm < 2; fm++)
                wmma::load_matrix_sync(af[fm], As + (wm * 32 + fm * 16) * 72 + kk, 72);
            #pragma unroll
            for (int fn = 0; fn < 4; fn++) {
                wmma::fragment<wmma::matrix_b, 16, 16, 16, __nv_bfloat16, wmma::col_major> bf;
                wmma::load_matrix_sync(bf, Bs + (wn * 64 + fn * 16) * 72 + kk, 72);
                #pragma unroll
                for (int fm = 0; fm < 2; fm++)
                    wmma::mma_sync(T.a[fm][fn], af[fm], bf, T.a[fm][fn]);
            }
        }
        __syncthreads();
        if (tid == 0 && kt + 2 < KT) issue(kt + 2, s);
    }
}

// ================= merged logit GEMM: head + compacted tails, ONE launch =================
// grid (157+235+391, 16). Tails early-exit row tiles beyond compacted count.
__global__ void __launch_bounds__(256, 2)
k_logit(const __nv_bfloat16* __restrict__ hpAll,
        const __nv_bfloat16* __restrict__ hp1C,
        const __nv_bfloat16* __restrict__ hp2C,
        const __nv_bfloat16* __restrict__ w0P, const float* __restrict__ b0,
        const __nv_bfloat16* __restrict__ w1P, const float* __restrict__ b1,
        const __nv_bfloat16* __restrict__ w2P, const float* __restrict__ b2)
{
    extern __shared__ __align__(128) char dsm[];
    const uint32_t sb = smem_u32(dsm);
    float* biasS = reinterpret_cast<float*>(dsm + 64);

    const int tid  = threadIdx.x;
    const int warp = tid >> 5;
    const int lane = tid & 31;
    const int wm   = warp & 3;
    const int wn   = warp >> 2;

    int x = blockIdx.x;
    int xo;
    const __nv_bfloat16* A; const __nv_bfloat16* B; const float* bias;
    const int* selc; const int* rows; float* selv; float* sumexp;
    int N, KT, ldA;
    if (x < 157) {
        xo = x; A = hpAll; B = w0P; bias = b0; N = 20000; KT = 16; ldA = 22;
        selc = g_selc0; rows = nullptr; selv = g_selh; sumexp = g_sum0;
    } else if (x < 392) {
        if ((int)blockIdx.y >= g_cnt[0]) return;
        xo = x - 157; A = hp1C; B = w1P; bias = b1; N = 30000; KT = 4; ldA = 4;
        selc = g_selc1; rows = g_rows1; selv = g_selv1; sumexp = g_sum1;
    } else {
        if ((int)blockIdx.y >= g_cnt[1]) return;
        xo = x - 392; A = hp2C; B = w2P; bias = b2; N = 50000; KT = 1; ldA = 1;
        selc = g_selc2; rows = g_rows2; selv = g_selv2; sumexp = g_sum2;
    }
    const int bm = blockIdx.y * 128;
    const int bn = xo * 128;

    if (tid == 0) { MBARRIER_INIT(sb, 1); MBARRIER_INIT(sb + 8, 1); }
    if (tid < 128) {
        int gc = bn + tid;
        biasS[tid] = (gc < N) ? bias[gc] : 0.f;
    }
    __syncthreads();

    AccTile T;
    gemm_mainloop(T, dsm, sb, A, B, blockIdx.y, xo, ldA, KT, KT, tid, wm, wn);

    // epilogue: per-warp staging overlaid on slab smem
    float* Cw = reinterpret_cast<float*>(dsm + 1024 + warp * 8704);
    #pragma unroll
    for (int fm = 0; fm < 2; fm++)
        #pragma unroll
        for (int fn = 0; fn < 4; fn++)
            wmma::store_matrix_sync(&Cw[(fm * 16) * 68 + fn * 16], T.a[fm][fn], 68,
                                    wmma::mem_row_major);
    __syncwarp();

    int r  = lane;
    int gr = bm + wm * 32 + r;
    int orow = rows ? rows[gr] : gr;        // map compacted row -> original row
    if (orow >= 0) {
        int sc = selc[orow];
        float rowsum = 0.f;
        #pragma unroll 8
        for (int c = 0; c < 64; c++) {
            int col128 = wn * 64 + c;
            int gc = bn + col128;
            if (gc < N) {
                float lg = Cw[r * 68 + c] + biasS[col128];
                rowsum += __expf(lg);
                if (gc == sc) selv[orow] = lg;
            }
        }
        atomicAdd(&sumexp[orow], rowsum);
    }
}

// ================= projection GEMM (unfused, packed bf16 out) =================
__global__ void __launch_bounds__(256, 2)
k_proj(const __nv_bfloat16* __restrict__ A,
       const __nv_bfloat16* __restrict__ B,
       __nv_bfloat16* __restrict__ Cp)
{
    extern __shared__ __align__(128) char dsm[];
    const uint32_t sb = smem_u32(dsm);
    const int tid  = threadIdx.x;
    const int warp = tid >> 5;
    const int lane = tid & 31;
    const int wm   = warp & 3;
    const int wn   = warp >> 2;
    const int bm   = blockIdx.y * 128;
    const int bn   = blockIdx.x * 128;

    if (tid == 0) { MBARRIER_INIT(sb, 1); MBARRIER_INIT(sb + 8, 1); }
    __syncthreads();

    AccTile T;
    gemm_mainloop(T, dsm, sb, A, B, blockIdx.y, blockIdx.x, 16, 16, 16, tid, wm, wn);

    float* Cw = reinterpret_cast<float*>(dsm + 1024 + warp * 8704);
    #pragma unroll
    for (int fm = 0; fm < 2; fm++)
        #pragma unroll
        for (int fn = 0; fn < 4; fn++)
            wmma::store_matrix_sync(&Cw[(fm * 16) * 68 + fn * 16], T.a[fm][fn], 68,
                                    wmma::mem_row_major);
    __syncwarp();

    int r  = lane;
    int gr = bm + wm * 32 + r;
    #pragma unroll 8
    for (int c = 0; c < 64; c++) {
        int gc = bn + wn * 64 + c;
        if (gc < 1408) {
            size_t doff = ((size_t)(gr >> 7) * 22 + (gc >> 6)) * SLAB_ELEMS
                          + (size_t)(gr & 127) * 72 + (gc & 63);
            Cp[doff] = __float2bfloat16(Cw[r * 68 + c]);
        }
    }
}

// ================= cluster logits (head cols 20000, 20001); hp0 = hpAll slabs 0..15 =======
__global__ void k_cluster(const __nv_bfloat16* __restrict__ hpAll,
                          const float* __restrict__ cw,
                          const float* __restrict__ cb)
{
    int row  = blockIdx.x * 8 + (threadIdx.x >> 5);
    int lane = threadIdx.x & 31;
    if (row >= NROWS) return;
    size_t rbase = (size_t)(row >> 7) * 22 * SLAB_ELEMS + (size_t)(row & 127) * 72;
    float s0 = 0.f, s1 = 0.f;
    for (int k = lane; k < DIM; k += 32) {
        float h = __bfloat162float(hpAll[rbase + (size_t)(k >> 6) * SLAB_ELEMS + (k & 63)]);
        s0 += h * cw[k];
        s1 += h * cw[DIM + k];
    }
    #pragma unroll
    for (int o = 16; o > 0; o >>= 1) {
        s0 += __shfl_xor_sync(0xffffffffu, s0, o);
        s1 += __shfl_xor_sync(0xffffffffu, s1, o);
    }
    if (lane == 0) {
        float c0 = s0 + cb[0];
        float c1 = s1 + cb[1];
        atomicAdd(&g_sum0[row], __expf(c0) + __expf(c1));
        int t = g_tgt[row];
        // reference quirk head_lp[:, -i]: tail1 -> col 20001 (c1); tail2 -> col 20000 (c0)
        if (t >= 50000)      g_selh[row] = c0;
        else if (t >= 20000) g_selh[row] = c1;
    }
}

// ================= finalize =================
__global__ void k_final(float* __restrict__ out) {
    int r = blockIdx.x * blockDim.x + threadIdx.x;
    if (r >= NROWS) return;
    int t = g_tgt[r];
    float lse0 = logf(g_sum0[r]);
    float nll;
    if (t < 20000)
        nll = -(g_selh[r] - lse0);
    else if (t < 50000)
        nll = -((g_selh[r] - lse0) + (g_selv1[r] - logf(g_sum1[r])));
    else
        nll = -((g_selh[r] - lse0) + (g_selv2[r] - logf(g_sum2[r])));
    out[r] = nll;
}

// ================= launch =================
static inline void* sym(const void* s) {
    void* p = nullptr;
    cudaGetSymbolAddress(&p, s);
    return p;
}

extern "C" void kernel_launch(void* const* d_in, const int* in_sizes, int n_in,
                              void* d_out, int out_size)
{
    const float* hidden = (const float*)d_in[0];
    const int*   target = (const int*)d_in[1];
    const float* w0     = (const float*)d_in[2];
    const float* b0     = (const float*)d_in[3];
    const float* cw     = (const float*)d_in[4];
    const float* cb     = (const float*)d_in[5];
    const float* p0     = (const float*)d_in[6];
    const float* w1     = (const float*)d_in[7];
    const float* b1     = (const float*)d_in[8];
    const float* p1     = (const float*)d_in[9];
    const float* w2     = (const float*)d_in[10];
    const float* b2     = (const float*)d_in[11];
    const float* p2     = (const float*)d_in[12];
    float* out = (float*)d_out;

    __nv_bfloat16* hP    = (__nv_bfloat16*)sym(g_hP);
    __nv_bfloat16* pT    = (__nv_bfloat16*)sym(g_pT);
    __nv_bfloat16* w0P   = (__nv_bfloat16*)sym(g_w0P);
    __nv_bfloat16* w1P   = (__nv_bfloat16*)sym(g_w1P);
    __nv_bfloat16* w2P   = (__nv_bfloat16*)sym(g_w2P);
    __nv_bfloat16* hpAll = (__nv_bfloat16*)sym(g_hpAll);
    __nv_bfloat16* hp1C  = (__nv_bfloat16*)sym(g_hp1C);
    __nv_bfloat16* hp2C  = (__nv_bfloat16*)sym(g_hp2C);

    const int SMEM_WM = 1024 + 4 * SLAB_BYTES;   // 74752 (2 stages; epilogue overlays slabs)
    cudaFuncSetAttribute(k_logit, cudaFuncAttributeMaxDynamicSharedMemorySize, SMEM_WM);
    cudaFuncSetAttribute(k_proj,  cudaFuncAttributeMaxDynamicSharedMemorySize, SMEM_WM);

    // 0: all row-major packs (h, w0, w1, w2)
    k_packAll<<<dim3(8, 391, 4), 256>>>(hidden, hP, w0, w0P, w1, w1P, w2, w2P);
    // 1: transpose-pack p0|p1|p2 + target decode/init + row compaction
    k_packT_init<<<dim3(45, 32), dim3(32, 8)>>>(p0, p1, p2, pT, target);
    // 2: fused projection GEMM -> hpAll [2048, 1408 packed, ldC=22]
    k_proj<<<dim3(11, 16), 256, SMEM_WM>>>(hP, pT, hpAll);
    // 3: gather compacted tail rows
    k_gather<<<dim3(16, 2), 256>>>(hpAll, hp1C, hp2C);
    // 4: MERGED logit GEMM (head full + tails compacted)
    k_logit<<<dim3(157 + 235 + 391, 16), 256, SMEM_WM>>>(hpAll, hp1C, hp2C,
                                                         w0P, b0, w1P, b1, w2P, b2);
    // 5: cluster logits
    k_cluster<<<NROWS / 8, 256>>>(hpAll, cw, cb);
    // 6: finalize
    k_final<<<(NROWS + 255) / 256, 256>>>(out);
}

// round 16
// speedup vs baseline: 1.4945x; 1.0124x over previous
#include <cuda_runtime.h>
#include <cuda_bf16.h>
#include <mma.h>
#include <cstdint>

using namespace nvcuda;

#define NROWS 2048
#define DIM   1024

// Packed slab layout: matrix [Rpad, K] (K-major) stored as slabs of 128 rows x 64 K.
// Within a row-tile rt, slab kt lives at ((rt*ld)+kt)*SLAB_ELEMS (ld = slabs per row-tile).
// Row r at r*72 elems (144B stride), col c at +c. Slab = 18432B contiguous -> one bulk copy.
#define SLAB_ELEMS 9216
#define SLAB_BYTES 18432

// ================= helpers =================
__device__ __forceinline__ uint32_t smem_u32(const void* p) {
    uint32_t a;
    asm("{ .reg .u64 t; cvta.to.shared.u64 t, %1; cvt.u32.u64 %0, t; }" : "=r"(a) : "l"(p));
    return a;
}
#define MBARRIER_INIT(mbar, cnt) \
    asm volatile("mbarrier.init.shared.b64 [%0], %1;" \
                 :: "r"((uint32_t)(mbar)), "r"((uint32_t)(cnt)) : "memory")
#define MBARRIER_EXPECT_TX(mbar, tx) \
    asm volatile("mbarrier.arrive.expect_tx.shared.b64 _, [%0], %1;" \
                 :: "r"((uint32_t)(mbar)), "r"((uint32_t)(tx)) : "memory")
#define MBARRIER_WAIT_PARITY(mbar, par) do { \
    uint32_t _m = (uint32_t)(mbar); uint32_t _p = (uint32_t)(par); uint32_t _d; \
    asm volatile("{\n\t.reg .pred p;\n\t" \
        "mbarrier.try_wait.parity.acquire.cta.shared::cta.b64 p, [%1], %2;\n\t" \
        "selp.b32 %0, 1, 0, p;\n\t}" : "=r"(_d) : "r"(_m), "r"(_p) : "memory"); \
    if (!_d) { \
        asm volatile("{\n\t.reg .pred P1;\n\t" \
            "WL_%=:\n\t" \
            "mbarrier.try_wait.parity.acquire.cta.shared::cta.b64 P1, [%0], %1, 0x989680;\n\t" \
            "@P1 bra.uni WD_%=;\n\t" \
            "bra.uni WL_%=;\n\t" \
            "WD_%=:\n\t}" :: "r"(_m), "r"(_p) : "memory"); \
    } \
} while (0)
__device__ __forceinline__ void bulk_g2s(uint32_t dst, const void* src, uint32_t bytes,
                                         uint32_t mbar) {
    asm volatile(
        "cp.async.bulk.shared::cluster.global.mbarrier::complete_tx::bytes [%0], [%1], %2, [%3];"
        :: "r"(dst), "l"(src), "r"(bytes), "r"(mbar) : "memory");
}

// ================= packed scratch buffers (bf16) =================
__device__ __align__(256) __nv_bfloat16 g_hP   [16 * 16 * SLAB_ELEMS];   // h [2048,1024]
__device__ __align__(256) __nv_bfloat16 g_pT   [11 * 16 * SLAB_ELEMS];   // projT cat [1408,1024]
__device__ __align__(256) __nv_bfloat16 g_w0P  [157 * 16 * SLAB_ELEMS];
__device__ __align__(256) __nv_bfloat16 g_w1P  [235 *  4 * SLAB_ELEMS];
__device__ __align__(256) __nv_bfloat16 g_w2P  [391 *  1 * SLAB_ELEMS];
__device__ __align__(256) __nv_bfloat16 g_hpAll[16 * 16 * SLAB_ELEMS];   // hp head [2048,1024]
__device__ __align__(256) __nv_bfloat16 g_hp1C [16 *  4 * SLAB_ELEMS];   // compacted tail1 rows
__device__ __align__(256) __nv_bfloat16 g_hp2C [16 *  1 * SLAB_ELEMS];   // compacted tail2 rows
__device__ __align__(256) float g_sum0[NROWS];
__device__ __align__(256) float g_sum1[NROWS];
__device__ __align__(256) float g_sum2[NROWS];
__device__ __align__(256) float g_selh [NROWS];
__device__ __align__(256) float g_selv1[NROWS];
__device__ __align__(256) float g_selv2[NROWS];
__device__ __align__(256) int   g_selc0[NROWS];
__device__ __align__(256) int   g_selc1[NROWS];
__device__ __align__(256) int   g_selc2[NROWS];
__device__ __align__(256) int   g_tgt  [NROWS];
__device__ __align__(256) int   g_rows1[NROWS];   // compacted row lists (-1 pad)
__device__ __align__(256) int   g_rows2[NROWS];
__device__ __align__(256) int   g_inv1[NROWS];    // orig row -> compact idx (-1 if none)
__device__ __align__(256) int   g_inv2[NROWS];
__device__ __align__(256) int   g_cnt[2];         // padded tile counts for tail1/tail2

// ======== packAll: 4 row-major fp32 matrices -> packed bf16 slabs in ONE launch ==========
__global__ void k_packAll(const float* __restrict__ h,  __nv_bfloat16* __restrict__ hP,
                          const float* __restrict__ w0, __nv_bfloat16* __restrict__ w0P,
                          const float* __restrict__ w1, __nv_bfloat16* __restrict__ w1P,
                          const float* __restrict__ w2, __nv_bfloat16* __restrict__ w2P)
{
    const float* src; __nv_bfloat16* dst; int R, K, tiles;
    switch (blockIdx.z) {
        case 0: src = h;  dst = hP;  R = 2048;  K = 1024; tiles = 16;  break;
        case 1: src = w0; dst = w0P; R = 20000; K = 1024; tiles = 157; break;
        case 2: src = w1; dst = w1P; R = 30000; K = 256;  tiles = 235; break;
        default:src = w2; dst = w2P; R = 50000; K = 64;   tiles = 391; break;
    }
    if ((int)blockIdx.y >= tiles) return;
    int chunksPerRow = K >> 3;
    int shift = 31 - __clz(chunksPerRow);
    int blockChunks = chunksPerRow << 7;
    int rbase = blockIdx.y << 7;
    for (int idx = blockIdx.x * blockDim.x + threadIdx.x; idx < blockChunks;
         idx += gridDim.x * blockDim.x) {
        int rloc = idx >> shift;
        int c    = idx & (chunksPerRow - 1);
        int r    = rbase + rloc;
        int kt = c >> 3, ci = c & 7;
        size_t doff = ((size_t)blockIdx.y * (K >> 6) + kt) * SLAB_ELEMS
                      + (size_t)rloc * 72 + ci * 8;
        uint4 o = make_uint4(0u, 0u, 0u, 0u);
        if (r < R) {
            const float4* s = reinterpret_cast<const float4*>(src + (size_t)r * K + c * 8);
            float4 v0 = s[0], v1 = s[1];
            __nv_bfloat162 b0 = __floats2bfloat162_rn(v0.x, v0.y);
            __nv_bfloat162 b1 = __floats2bfloat162_rn(v0.z, v0.w);
            __nv_bfloat162 b2 = __floats2bfloat162_rn(v1.x, v1.y);
            __nv_bfloat162 b3 = __floats2bfloat162_rn(v1.z, v1.w);
            o.x = *reinterpret_cast<uint32_t*>(&b0);
            o.y = *reinterpret_cast<uint32_t*>(&b1);
            o.z = *reinterpret_cast<uint32_t*>(&b2);
            o.w = *reinterpret_cast<uint32_t*>(&b3);
        }
        *reinterpret_cast<uint4*>(dst + doff) = o;
    }
}

// ======== packT_init: transpose-pack p0|p1|p2 -> g_pT + target decode + row compaction ====
__global__ void k_packT_init(const float* __restrict__ p0, const float* __restrict__ p1,
                             const float* __restrict__ p2, __nv_bfloat16* __restrict__ pT,
                             const int* __restrict__ t32)
{
    if (blockIdx.x == 44) {
        if (blockIdx.y != 0) return;
        int tid = threadIdx.y * 32 + threadIdx.x;
        __shared__ int s_nonzero_odd, s_c1, s_c2;
        if (tid == 0) { s_nonzero_odd = 0; s_c1 = 0; s_c2 = 0; }
        __syncthreads();
        for (int i = tid; i < NROWS / 2; i += 256)
            if (t32[2 * i + 1] != 0) atomicOr(&s_nonzero_odd, 1);
        __syncthreads();
        bool is64 = (s_nonzero_odd == 0);
        for (int r = tid; r < NROWS; r += 256) {
            int t = is64 ? t32[2 * r] : t32[r];
            g_tgt[r] = t;
            g_sum0[r] = 0.f; g_sum1[r] = 0.f; g_sum2[r] = 0.f;
            g_selc0[r] = (t < 20000) ? t : -1;
            int t1 = t - 20000; if (t1 < 0) t1 = 0; if (t1 > 29999) t1 = 29999;
            g_selc1[r] = t1;
            int t2 = t - 50000; if (t2 < 0) t2 = 0; if (t2 > 49999) t2 = 49999;
            g_selc2[r] = t2;
            int i1 = -1, i2 = -1;
            if (t >= 20000 && t < 50000) { i1 = atomicAdd(&s_c1, 1); g_rows1[i1] = r; }
            else if (t >= 50000)         { i2 = atomicAdd(&s_c2, 1); g_rows2[i2] = r; }
            g_inv1[r] = i1;
            g_inv2[r] = i2;
        }
        __syncthreads();
        int c1 = s_c1, c2 = s_c2;
        int p1n = (c1 + 127) & ~127, p2n = (c2 + 127) & ~127;
        for (int i = c1 + tid; i < p1n; i += 256) g_rows1[i] = -1;
        for (int i = c2 + tid; i < p2n; i += 256) g_rows2[i] = -1;
        if (tid == 0) { g_cnt[0] = p1n >> 7; g_cnt[1] = p2n >> 7; }
        return;
    }
    __shared__ float t[32][33];
    int n0 = blockIdx.x * 32, k0 = blockIdx.y * 32;
    int x = threadIdx.x, y = threadIdx.y;
    #pragma unroll
    for (int i = 0; i < 32; i += 8) {
        int k = k0 + y + i, n = n0 + x;
        float v;
        if (n < 1024)       v = p0[(size_t)k * 1024 + n];
        else if (n < 1280)  v = p1[(size_t)k * 256 + (n - 1024)];
        else if (n < 1344)  v = p2[(size_t)k * 64 + (n - 1280)];
        else                v = 0.f;
        t[y + i][x] = v;
    }
    __syncthreads();
    #pragma unroll
    for (int i = 0; i < 32; i += 8) {
        int n = n0 + y + i, k = k0 + x;
        size_t doff = ((size_t)(n >> 7) * 16 + (k >> 6)) * SLAB_ELEMS
                      + (size_t)(n & 127) * 72 + (k & 63);
        pT[doff] = __float2bfloat16(t[x][y + i]);
    }
}

// ================= shared GEMM mainloop (2-stage bulk pipeline) =================
struct AccTile {
    wmma::fragment<wmma::accumulator, 16, 16, 16, float> a[2][4];
};
__device__ __forceinline__ void gemm_mainloop(
    AccTile& T, char* dsm, uint32_t sb,
    const __nv_bfloat16* A, const __nv_bfloat16* B,
    int rowTile, int colTile, int ldA, int ldB, int KT,
    int tid, int wm, int wn)
{
    auto slabA = [&](int s) {
        return reinterpret_cast<const __nv_bfloat16*>(dsm + 1024 + s * 2 * SLAB_BYTES);
    };
    auto slabB = [&](int s) {
        return reinterpret_cast<const __nv_bfloat16*>(dsm + 1024 + s * 2 * SLAB_BYTES + SLAB_BYTES);
    };
    auto issue = [&](int kt, int s) {
        uint32_t mb = sb + (uint32_t)s * 8;
        MBARRIER_EXPECT_TX(mb, 2 * SLAB_BYTES);
        const char* aS = reinterpret_cast<const char*>(A)
                         + ((size_t)rowTile * ldA + kt) * SLAB_BYTES;
        const char* bS = reinterpret_cast<const char*>(B)
                         + ((size_t)colTile * ldB + kt) * SLAB_BYTES;
        bulk_g2s(smem_u32(slabA(s)), aS, SLAB_BYTES, mb);
        bulk_g2s(smem_u32(slabB(s)), bS, SLAB_BYTES, mb);
    };
    if (tid == 0) { issue(0, 0); if (KT > 1) issue(1, 1); }

    #pragma unroll
    for (int fm = 0; fm < 2; fm++)
        #pragma unroll
        for (int fn = 0; fn < 4; fn++)
            wmma::fill_fragment(T.a[fm][fn], 0.f);

    for (int kt = 0; kt < KT; kt++) {
        int s = kt & 1;
        MBARRIER_WAIT_PARITY(sb + (uint32_t)s * 8, (kt >> 1) & 1);
        const __nv_bfloat16* As = slabA(s);
        const __nv_bfloat16* Bs = slabB(s);
        #pragma unroll
        for (int kk = 0; kk < 64; kk += 16) {
            wmma::fragment<wmma::matrix_a, 16, 16, 16, __nv_bfloat16, wmma::row_major> af[2];
            #pragma unroll
            for (int fm = 0; fm < 2; fm++)
                wmma::load_matrix_sync(af[fm], As + (wm * 32 + fm * 16) * 72 + kk, 72);
            #pragma unroll
            for (int fn = 0; fn < 4; fn++) {
                wmma::fragment<wmma::matrix_b, 16, 16, 16, __nv_bfloat16, wmma::col_major> bf;
                wmma::load_matrix_sync(bf, Bs + (wn * 64 + fn * 16) * 72 + kk, 72);
                #pragma unroll
                for (int fm = 0; fm < 2; fm++)
                    wmma::mma_sync(T.a[fm][fn], af[fm], bf, T.a[fm][fn]);
            }
        }
        __syncthreads();
        if (tid == 0 && kt + 2 < KT) issue(kt + 2, s);
    }
}

// ================= merged logit GEMM + cluster logits, ONE launch =================
// grid (784, 16): x<157 head; x<392 tail1 (compacted); x<783 tail2 (compacted);
// x==783 cluster-logit segment (row block per y).
__global__ void __launch_bounds__(256, 2)
k_logit(const __nv_bfloat16* __restrict__ hpAll,
        const __nv_bfloat16* __restrict__ hp1C,
        const __nv_bfloat16* __restrict__ hp2C,
        const __nv_bfloat16* __restrict__ w0P, const float* __restrict__ b0,
        const __nv_bfloat16* __restrict__ w1P, const float* __restrict__ b1,
        const __nv_bfloat16* __restrict__ w2P, const float* __restrict__ b2,
        const float* __restrict__ cw, const float* __restrict__ cb)
{
    extern __shared__ __align__(128) char dsm[];
    const uint32_t sb = smem_u32(dsm);
    float* biasS = reinterpret_cast<float*>(dsm + 64);

    const int tid  = threadIdx.x;
    const int warp = tid >> 5;
    const int lane = tid & 31;

    int x = blockIdx.x;

    if (x == 783) {
        // ---- cluster logits: rows bm..bm+127, warp handles 16 rows ----
        int bm = blockIdx.y * 128;
        for (int i = 0; i < 16; i++) {
            int row = bm + warp * 16 + i;
            size_t rbase = (size_t)(row >> 7) * 16 * SLAB_ELEMS + (size_t)(row & 127) * 72;
            float s0 = 0.f, s1 = 0.f;
            for (int k = lane; k < DIM; k += 32) {
                float h = __bfloat162float(hpAll[rbase + (size_t)(k >> 6) * SLAB_ELEMS + (k & 63)]);
                s0 += h * cw[k];
                s1 += h * cw[DIM + k];
            }
            #pragma unroll
            for (int o = 16; o > 0; o >>= 1) {
                s0 += __shfl_xor_sync(0xffffffffu, s0, o);
                s1 += __shfl_xor_sync(0xffffffffu, s1, o);
            }
            if (lane == 0) {
                float c0 = s0 + cb[0];   // head col 20000
                float c1 = s1 + cb[1];   // head col 20001
                atomicAdd(&g_sum0[row], __expf(c0) + __expf(c1));
                int t = g_tgt[row];
                // quirk head_lp[:, -i]: tail1 -> col 20001 (c1); tail2 -> col 20000 (c0)
                if (t >= 50000)      g_selh[row] = c0;
                else if (t >= 20000) g_selh[row] = c1;
            }
        }
        return;
    }

    const int wm = warp & 3;
    const int wn = warp >> 2;
    int xo;
    const __nv_bfloat16* A; const __nv_bfloat16* B; const float* bias;
    const int* selc; const int* rows; float* selv; float* sumexp;
    int N, KT, ldA;
    if (x < 157) {
        xo = x; A = hpAll; B = w0P; bias = b0; N = 20000; KT = 16; ldA = 16;
        selc = g_selc0; rows = nullptr; selv = g_selh; sumexp = g_sum0;
    } else if (x < 392) {
        if ((int)blockIdx.y >= g_cnt[0]) return;
        xo = x - 157; A = hp1C; B = w1P; bias = b1; N = 30000; KT = 4; ldA = 4;
        selc = g_selc1; rows = g_rows1; selv = g_selv1; sumexp = g_sum1;
    } else {
        if ((int)blockIdx.y >= g_cnt[1]) return;
        xo = x - 392; A = hp2C; B = w2P; bias = b2; N = 50000; KT = 1; ldA = 1;
        selc = g_selc2; rows = g_rows2; selv = g_selv2; sumexp = g_sum2;
    }
    const int bm = blockIdx.y * 128;
    const int bn = xo * 128;

    if (tid == 0) { MBARRIER_INIT(sb, 1); MBARRIER_INIT(sb + 8, 1); }
    if (tid < 128) {
        int gc = bn + tid;
        biasS[tid] = (gc < N) ? bias[gc] : 0.f;
    }
    __syncthreads();

    AccTile T;
    gemm_mainloop(T, dsm, sb, A, B, blockIdx.y, xo, ldA, KT, KT, tid, wm, wn);

    // epilogue: per-warp staging overlaid on slab smem
    float* Cw = reinterpret_cast<float*>(dsm + 1024 + warp * 8704);
    #pragma unroll
    for (int fm = 0; fm < 2; fm++)
        #pragma unroll
        for (int fn = 0; fn < 4; fn++)
            wmma::store_matrix_sync(&Cw[(fm * 16) * 68 + fn * 16], T.a[fm][fn], 68,
                                    wmma::mem_row_major);
    __syncwarp();

    int r  = lane;
    int gr = bm + wm * 32 + r;
    int orow = rows ? rows[gr] : gr;        // map compacted row -> original row
    if (orow >= 0) {
        int sc = selc[orow];
        float rowsum = 0.f;
        #pragma unroll 8
        for (int c = 0; c < 64; c++) {
            int col128 = wn * 64 + c;
            int gc = bn + col128;
            if (gc < N) {
                float lg = Cw[r * 68 + c] + biasS[col128];
                rowsum += __expf(lg);
                if (gc == sc) selv[orow] = lg;
            }
        }
        atomicAdd(&sumexp[orow], rowsum);
    }
}

// ================= projection GEMM: scatter head cols to hpAll, tail cols compacted =======
__global__ void __launch_bounds__(256, 2)
k_proj(const __nv_bfloat16* __restrict__ A,
       const __nv_bfloat16* __restrict__ B,
       __nv_bfloat16* __restrict__ hpAll,
       __nv_bfloat16* __restrict__ hp1C,
       __nv_bfloat16* __restrict__ hp2C)
{
    extern __shared__ __align__(128) char dsm[];
    const uint32_t sb = smem_u32(dsm);
    const int tid  = threadIdx.x;
    const int warp = tid >> 5;
    const int lane = tid & 31;
    const int wm   = warp & 3;
    const int wn   = warp >> 2;
    const int bm   = blockIdx.y * 128;
    const int bn   = blockIdx.x * 128;

    if (tid == 0) { MBARRIER_INIT(sb, 1); MBARRIER_INIT(sb + 8, 1); }
    __syncthreads();

    AccTile T;
    gemm_mainloop(T, dsm, sb, A, B, blockIdx.y, blockIdx.x, 16, 16, 16, tid, wm, wn);

    float* Cw = reinterpret_cast<float*>(dsm + 1024 + warp * 8704);
    #pragma unroll
    for (int fm = 0; fm < 2; fm++)
        #pragma unroll
        for (int fn = 0; fn < 4; fn++)
            wmma::store_matrix_sync(&Cw[(fm * 16) * 68 + fn * 16], T.a[fm][fn], 68,
                                    wmma::mem_row_major);
    __syncwarp();

    int r  = lane;
    int gr = bm + wm * 32 + r;
    int i1 = g_inv1[gr];
    int i2 = g_inv2[gr];
    #pragma unroll 8
    for (int c = 0; c < 64; c++) {
        int gc = bn + wn * 64 + c;
        __nv_bfloat16 v = __float2bfloat16(Cw[r * 68 + c]);
        if (gc < 1024) {
            size_t doff = ((size_t)(gr >> 7) * 16 + (gc >> 6)) * SLAB_ELEMS
                          + (size_t)(gr & 127) * 72 + (gc & 63);
            hpAll[doff] = v;
        } else if (gc < 1280) {
            if (i1 >= 0) {
                int k = gc - 1024;
                size_t doff = ((size_t)(i1 >> 7) * 4 + (k >> 6)) * SLAB_ELEMS
                              + (size_t)(i1 & 127) * 72 + (k & 63);
                hp1C[doff] = v;
            }
        } else if (gc < 1344) {
            if (i2 >= 0) {
                int k = gc - 1280;
                size_t doff = (size_t)(i2 >> 7) * SLAB_ELEMS
                              + (size_t)(i2 & 127) * 72 + k;
                hp2C[doff] = v;
            }
        }
    }
}

// ================= finalize =================
__global__ void k_final(float* __restrict__ out) {
    int r = blockIdx.x * blockDim.x + threadIdx.x;
    if (r >= NROWS) return;
    int t = g_tgt[r];
    float lse0 = logf(g_sum0[r]);
    float nll;
    if (t < 20000)
        nll = -(g_selh[r] - lse0);
    else if (t < 50000)
        nll = -((g_selh[r] - lse0) + (g_selv1[r] - logf(g_sum1[r])));
    else
        nll = -((g_selh[r] - lse0) + (g_selv2[r] - logf(g_sum2[r])));
    out[r] = nll;
}

// ================= launch =================
static inline void* sym(const void* s) {
    void* p = nullptr;
    cudaGetSymbolAddress(&p, s);
    return p;
}

extern "C" void kernel_launch(void* const* d_in, const int* in_sizes, int n_in,
                              void* d_out, int out_size)
{
    const float* hidden = (const float*)d_in[0];
    const int*   target = (const int*)d_in[1];
    const float* w0     = (const float*)d_in[2];
    const float* b0     = (const float*)d_in[3];
    const float* cw     = (const float*)d_in[4];
    const float* cb     = (const float*)d_in[5];
    const float* p0     = (const float*)d_in[6];
    const float* w1     = (const float*)d_in[7];
    const float* b1     = (const float*)d_in[8];
    const float* p1     = (const float*)d_in[9];
    const float* w2     = (const float*)d_in[10];
    const float* b2     = (const float*)d_in[11];
    const float* p2     = (const float*)d_in[12];
    float* out = (float*)d_out;

    __nv_bfloat16* hP    = (__nv_bfloat16*)sym(g_hP);
    __nv_bfloat16* pT    = (__nv_bfloat16*)sym(g_pT);
    __nv_bfloat16* w0P   = (__nv_bfloat16*)sym(g_w0P);
    __nv_bfloat16* w1P   = (__nv_bfloat16*)sym(g_w1P);
    __nv_bfloat16* w2P   = (__nv_bfloat16*)sym(g_w2P);
    __nv_bfloat16* hpAll = (__nv_bfloat16*)sym(g_hpAll);
    __nv_bfloat16* hp1C  = (__nv_bfloat16*)sym(g_hp1C);
    __nv_bfloat16* hp2C  = (__nv_bfloat16*)sym(g_hp2C);

    const int SMEM_WM = 1024 + 4 * SLAB_BYTES;   // 74752 (2 stages; epilogue overlays slabs)
    cudaFuncSetAttribute(k_logit, cudaFuncAttributeMaxDynamicSharedMemorySize, SMEM_WM);
    cudaFuncSetAttribute(k_proj,  cudaFuncAttributeMaxDynamicSharedMemorySize, SMEM_WM);

    // 0: all row-major packs (h, w0, w1, w2)
    k_packAll<<<dim3(8, 391, 4), 256>>>(hidden, hP, w0, w0P, w1, w1P, w2, w2P);
    // 1: transpose-pack p0|p1|p2 + target decode/init + row compaction + inverse maps
    k_packT_init<<<dim3(45, 32), dim3(32, 8)>>>(p0, p1, p2, pT, target);
    // 2: projection GEMM -> hpAll (head cols) + hp1C/hp2C (tail cols, compacted directly)
    k_proj<<<dim3(11, 16), 256, SMEM_WM>>>(hP, pT, hpAll, hp1C, hp2C);
    // 3: MERGED logit GEMM (head + compacted tails) + cluster-logit segment
    k_logit<<<dim3(784, 16), 256, SMEM_WM>>>(hpAll, hp1C, hp2C,
                                             w0P, b0, w1P, b1, w2P, b2, cw, cb);
    // 4: finalize
    k_final<<<(NROWS + 255) / 256, 256>>>(out);
}